// round 1
// baseline (speedup 1.0000x reference)
#include <cuda_runtime.h>
#include <math.h>

#define B_  8
#define NW_ 64
#define P_  160
#define E_  512
#define H_  8
#define D_  64
#define M_  (B_*NW_*P_)          // 81920 rows
#define QKV_ELEMS (B_*H_*NW_*P_*D_)   // 41,943,040

// Scratch for projected Q/K/V in [B,H,NW,P,D] layout (contiguous per (b,h,w) tile)
__device__ float g_q[QKV_ELEMS];
__device__ float g_k[QKV_ELEMS];
__device__ float g_v[QKV_ELEMS];

// ---------------------------------------------------------------------------
// QKV projection: y[m,f] = sum_e x[m,e]*w[f,e] + b[f]
// Tiled 64x64 output per block, BK=16, 256 threads, 4x4 microtile per thread.
// Stores directly into [B,H,NW,P,D] scratch.
// ---------------------------------------------------------------------------
__global__ __launch_bounds__(256) void qkv_kernel(
    const float* __restrict__ x,
    const float* __restrict__ wq, const float* __restrict__ bq,
    const float* __restrict__ wk, const float* __restrict__ bk,
    const float* __restrict__ wv, const float* __restrict__ bv)
{
    __shared__ float As[16][68];   // transposed: As[k][m], padded row (272B, 16B aligned)
    __shared__ float Bs[16][68];   // transposed: Bs[k][n]

    const float* wgt; const float* bias; float* outp;
    if (blockIdx.z == 0)      { wgt = wq; bias = bq; outp = g_q; }
    else if (blockIdx.z == 1) { wgt = wk; bias = bk; outp = g_k; }
    else                      { wgt = wv; bias = bv; outp = g_v; }

    const int m0 = blockIdx.y * 64;
    const int f0 = blockIdx.x * 64;
    const int tid = threadIdx.x;
    const int tx = tid & 15, ty = tid >> 4;
    const int lrow = tid >> 2;          // 0..63
    const int lseg = (tid & 3) * 4;     // 0,4,8,12

    float acc[4][4];
#pragma unroll
    for (int i = 0; i < 4; i++)
#pragma unroll
        for (int j = 0; j < 4; j++) acc[i][j] = 0.0f;

    const float* xa = x   + (size_t)(m0 + lrow) * E_ + lseg;
    const float* wb = wgt + (size_t)(f0 + lrow) * E_ + lseg;

    for (int kt = 0; kt < E_; kt += 16) {
        float4 a4 = *(const float4*)(xa + kt);
        float4 b4 = *(const float4*)(wb + kt);
        __syncthreads();
        As[lseg + 0][lrow] = a4.x;
        As[lseg + 1][lrow] = a4.y;
        As[lseg + 2][lrow] = a4.z;
        As[lseg + 3][lrow] = a4.w;
        Bs[lseg + 0][lrow] = b4.x;
        Bs[lseg + 1][lrow] = b4.y;
        Bs[lseg + 2][lrow] = b4.z;
        Bs[lseg + 3][lrow] = b4.w;
        __syncthreads();
#pragma unroll
        for (int kk = 0; kk < 16; kk++) {
            float4 av  = *(const float4*)&As[kk][ty * 4];
            float4 bv4 = *(const float4*)&Bs[kk][tx * 4];
            acc[0][0] = fmaf(av.x, bv4.x, acc[0][0]);
            acc[0][1] = fmaf(av.x, bv4.y, acc[0][1]);
            acc[0][2] = fmaf(av.x, bv4.z, acc[0][2]);
            acc[0][3] = fmaf(av.x, bv4.w, acc[0][3]);
            acc[1][0] = fmaf(av.y, bv4.x, acc[1][0]);
            acc[1][1] = fmaf(av.y, bv4.y, acc[1][1]);
            acc[1][2] = fmaf(av.y, bv4.z, acc[1][2]);
            acc[1][3] = fmaf(av.y, bv4.w, acc[1][3]);
            acc[2][0] = fmaf(av.z, bv4.x, acc[2][0]);
            acc[2][1] = fmaf(av.z, bv4.y, acc[2][1]);
            acc[2][2] = fmaf(av.z, bv4.z, acc[2][2]);
            acc[2][3] = fmaf(av.z, bv4.w, acc[2][3]);
            acc[3][0] = fmaf(av.w, bv4.x, acc[3][0]);
            acc[3][1] = fmaf(av.w, bv4.y, acc[3][1]);
            acc[3][2] = fmaf(av.w, bv4.z, acc[3][2]);
            acc[3][3] = fmaf(av.w, bv4.w, acc[3][3]);
        }
    }

    // Epilogue: add bias, scatter into [B,H,NW,P,D]
    const int hh = f0 >> 6;            // f0 is a multiple of 64
    float bb4[4];
#pragma unroll
    for (int j = 0; j < 4; j++) bb4[j] = bias[f0 + tx * 4 + j];

#pragma unroll
    for (int i = 0; i < 4; i++) {
        int m   = m0 + ty * 4 + i;
        int bi  = m / (NW_ * P_);
        int rem = m - bi * (NW_ * P_);
        int ww  = rem / P_;
        int p   = rem - ww * P_;
        float4 o;
        o.x = acc[i][0] + bb4[0];
        o.y = acc[i][1] + bb4[1];
        o.z = acc[i][2] + bb4[2];
        o.w = acc[i][3] + bb4[3];
        size_t oidx = (((size_t)(bi * H_ + hh) * NW_ + ww) * P_ + p) * D_ + tx * 4;
        *(float4*)(outp + oidx) = o;
    }
}

// ---------------------------------------------------------------------------
// Attention: one block per (b,h,w). S=QK^T*scale + bias, mask, softmax, O=PV.
// Dynamic shared: Qs[160][68] | KV (Kt[64][161] then Vs[160][68]) | Ss[160][161]
// ---------------------------------------------------------------------------
#define SMEM_FLOATS (10880 + 10880 + 25760)
#define SMEM_BYTES  (SMEM_FLOATS * 4)

__global__ __launch_bounds__(256) void attn_kernel(
    const float* __restrict__ pos_bias,
    float* __restrict__ out)
{
    extern __shared__ float sm[];
    float* Qs = sm;            // [160][68]
    float* KV = sm + 10880;    // Kt: [64][161] (10304 used), later Vs: [160][68]
    float* Ss = sm + 21760;    // [160][161]
    __shared__ float pb[19 * 31];
    __shared__ float rsum[160];

    const int w = blockIdx.x, h = blockIdx.y, b = blockIdx.z;
    const int tid = threadIdx.x;
    const int tx = tid & 15, ty = tid >> 4;

    for (int i = tid; i < 19 * 31; i += 256) pb[i] = pos_bias[i];

    const size_t base = ((size_t)(b * H_ + h) * NW_ + w) * (P_ * D_);
    const float* qg = g_q + base;
    const float* kg = g_k + base;
    const float* vg = g_v + base;

    // Load Q (pre-scaled by 1/sqrt(D)) and K transposed.
    for (int i = tid; i < P_ * D_ / 4; i += 256) {
        int e = i * 4;
        int p = e >> 6;
        int d = e & 63;
        float4 q4 = *(const float4*)(qg + e);
        q4.x *= 0.125f; q4.y *= 0.125f; q4.z *= 0.125f; q4.w *= 0.125f;
        *(float4*)(Qs + p * 68 + d) = q4;
        float4 k4 = *(const float4*)(kg + e);
        KV[(d + 0) * 161 + p] = k4.x;
        KV[(d + 1) * 161 + p] = k4.y;
        KV[(d + 2) * 161 + p] = k4.z;
        KV[(d + 3) * 161 + p] = k4.w;
    }
    __syncthreads();

    // S = Q K^T  (10x10 microtile per thread)
    float acc[10][10];
#pragma unroll
    for (int a = 0; a < 10; a++)
#pragma unroll
        for (int c = 0; c < 10; c++) acc[a][c] = 0.0f;

    const int i0 = ty * 10, j0 = tx * 10;
    for (int d = 0; d < 64; d++) {
        float qa[10], kb[10];
#pragma unroll
        for (int a = 0; a < 10; a++) qa[a] = Qs[(i0 + a) * 68 + d];
#pragma unroll
        for (int c = 0; c < 10; c++) kb[c] = KV[d * 161 + j0 + c];
#pragma unroll
        for (int a = 0; a < 10; a++)
#pragma unroll
            for (int c = 0; c < 10; c++)
                acc[a][c] = fmaf(qa[a], kb[c], acc[a][c]);
    }

    // Bias + analytic shift-mask, store S
    const int wy = w >> 3, wx = w & 7;
#pragma unroll
    for (int a = 0; a < 10; a++) {
        int i = i0 + a;
        int vi = i >> 4, hi = i & 15;     // WH=16: p = v*16 + h
#pragma unroll
        for (int c = 0; c < 10; c++) {
            int j = j0 + c;
            int vj = j >> 4, hj = j & 15;
            int dv = vj - vi + 19; if (dv >= 19) dv -= 19;
            int dh = hj - hi + 31; if (dh >= 31) dh -= 31;
            float s = acc[a][c] + pb[dv * 31 + dh];
            bool msk = ((wy == 7) && ((vi < 5) != (vj < 5))) ||
                       ((wx == 7) && ((hi < 8) != (hj < 8)));
            Ss[i * 161 + j] = msk ? -INFINITY : s;
        }
    }
    __syncthreads();

    // Load V into KV region (Kt no longer needed)
    for (int i = tid; i < P_ * D_ / 4; i += 256) {
        int e = i * 4;
        int p = e >> 6;
        int d = e & 63;
        *(float4*)(KV + p * 68 + d) = *(const float4*)(vg + e);
    }

    // Softmax (one warp per row group; 8 warps x 20 rows)
    const int lane = tid & 31, warp = tid >> 5;
    for (int r = warp; r < P_; r += 8) {
        float vals[5];
        float mx = -INFINITY;
#pragma unroll
        for (int c = 0; c < 5; c++) {
            vals[c] = Ss[r * 161 + lane + 32 * c];
            mx = fmaxf(mx, vals[c]);
        }
#pragma unroll
        for (int o = 16; o > 0; o >>= 1)
            mx = fmaxf(mx, __shfl_xor_sync(0xffffffffu, mx, o));
        float sum = 0.0f;
#pragma unroll
        for (int c = 0; c < 5; c++) {
            float e = __expf(vals[c] - mx);
            vals[c] = e;
            sum += e;
        }
#pragma unroll
        for (int o = 16; o > 0; o >>= 1)
            sum += __shfl_xor_sync(0xffffffffu, sum, o);
#pragma unroll
        for (int c = 0; c < 5; c++) Ss[r * 161 + lane + 32 * c] = vals[c];
        if (lane == 0) rsum[r] = 1.0f / sum;
    }
    __syncthreads();

    // O = P V  (10 rows x 4 cols per thread), normalize by row sum at the end
    float oacc[10][4];
#pragma unroll
    for (int a = 0; a < 10; a++)
#pragma unroll
        for (int j = 0; j < 4; j++) oacc[a][j] = 0.0f;

    for (int k = 0; k < P_; k++) {
        float4 v4 = *(const float4*)(KV + k * 68 + tx * 4);
#pragma unroll
        for (int a = 0; a < 10; a++) {
            float s = Ss[(i0 + a) * 161 + k];
            oacc[a][0] = fmaf(s, v4.x, oacc[a][0]);
            oacc[a][1] = fmaf(s, v4.y, oacc[a][1]);
            oacc[a][2] = fmaf(s, v4.z, oacc[a][2]);
            oacc[a][3] = fmaf(s, v4.w, oacc[a][3]);
        }
    }

    float* og = out + ((size_t)(b * NW_ + w) * P_) * E_ + h * D_ + tx * 4;
#pragma unroll
    for (int a = 0; a < 10; a++) {
        int i = i0 + a;
        float inv = rsum[i];
        float4 o4;
        o4.x = oacc[a][0] * inv;
        o4.y = oacc[a][1] * inv;
        o4.z = oacc[a][2] * inv;
        o4.w = oacc[a][3] * inv;
        *(float4*)(og + (size_t)i * E_) = o4;
    }
}

// ---------------------------------------------------------------------------
extern "C" void kernel_launch(void* const* d_in, const int* in_sizes, int n_in,
                              void* d_out, int out_size)
{
    const float* patches  = (const float*)d_in[0];
    const float* wq       = (const float*)d_in[1];
    const float* bq       = (const float*)d_in[2];
    const float* wk       = (const float*)d_in[3];
    const float* bk       = (const float*)d_in[4];
    const float* wv       = (const float*)d_in[5];
    const float* bv       = (const float*)d_in[6];
    const float* pos_bias = (const float*)d_in[7];
    float* out            = (float*)d_out;

    dim3 g1(E_ / 64, M_ / 64, 3);   // (8, 1280, 3)
    qkv_kernel<<<g1, 256>>>(patches, wq, bq, wk, bk, wv, bv);

    cudaFuncSetAttribute(attn_kernel,
                         cudaFuncAttributeMaxDynamicSharedMemorySize, SMEM_BYTES);
    dim3 g2(NW_, H_, B_);           // (64, 8, 8)
    attn_kernel<<<g2, 256, SMEM_BYTES>>>(pos_bias, out);
}

// round 4
// speedup vs baseline: 1.2429x; 1.2429x over previous
#include <cuda_runtime.h>
#include <math.h>
#include <stdint.h>

#define B_  8
#define NW_ 64
#define P_  160
#define E_  512
#define H_  8
#define D_  64
#define M_  (B_*NW_*P_)               // 81920 rows
#define QKV_ELEMS (B_*H_*NW_*P_*D_)   // 41,943,040

typedef unsigned long long ull;

// Scratch for projected Q/K/V in [B,H,NW,P,D] layout
__device__ float g_q[QKV_ELEMS];
__device__ float g_k[QKV_ELEMS];
__device__ float g_v[QKV_ELEMS];

// Packed f32x2 helpers (Blackwell baseline: fma.rn.f32x2 / mov.b64)
#define FMA2(c, a, b) asm("fma.rn.f32x2 %0, %1, %2, %3;" : "=l"(c) : "l"(a), "l"(b), "l"(c))
#define DUP2(d, f)    asm("mov.b64 %0, {%1, %1};" : "=l"(d) : "f"(f))
#define UNPK(lo, hi, v) asm("mov.b64 {%0, %1}, %2;" : "=f"(lo), "=f"(hi) : "l"(v))

// ---------------------------------------------------------------------------
// QKV projection: y[m,f] = sum_e x[m,e]*w[f,e] + b[f]
// 128x128 tile, BK=16, 256 threads, 8x8 microtile with f32x2 packed FMA.
// ---------------------------------------------------------------------------
__global__ __launch_bounds__(256, 2) void qkv_kernel(
    const float* __restrict__ x,
    const float* __restrict__ wq, const float* __restrict__ bq,
    const float* __restrict__ wk, const float* __restrict__ bk,
    const float* __restrict__ wv, const float* __restrict__ bv)
{
    __shared__ float As[16][136];   // [k][m], 136-stride keeps 16B row alignment
    __shared__ float Bs[16][136];   // [k][n]

    const float* wgt; const float* bias; float* outp;
    if (blockIdx.z == 0)      { wgt = wq; bias = bq; outp = g_q; }
    else if (blockIdx.z == 1) { wgt = wk; bias = bk; outp = g_k; }
    else                      { wgt = wv; bias = bv; outp = g_v; }

    const int m0 = blockIdx.x * 128;
    const int f0 = blockIdx.y * 128;
    const int tid = threadIdx.x;
    const int tx = tid & 15, ty = tid >> 4;
    const int la_m = tid >> 2;          // 0..63 (also +64)
    const int la_s = (tid & 3) * 4;     // k-seg 0,4,8,12

    ull acc[8][4];
#pragma unroll
    for (int i = 0; i < 8; i++)
#pragma unroll
        for (int j = 0; j < 4; j++) acc[i][j] = 0ull;

    const float* xa  = x   + (size_t)(m0 + la_m) * E_ + la_s;
    const float* xa2 = xa  + (size_t)64 * E_;
    const float* wa  = wgt + (size_t)(f0 + la_m) * E_ + la_s;
    const float* wa2 = wa  + (size_t)64 * E_;

    float4 pa0 = *(const float4*)(xa);
    float4 pa1 = *(const float4*)(xa2);
    float4 pb0 = *(const float4*)(wa);
    float4 pb1 = *(const float4*)(wa2);

    for (int kt = 0; kt < E_; kt += 16) {
        As[la_s + 0][la_m] = pa0.x;  As[la_s + 1][la_m] = pa0.y;
        As[la_s + 2][la_m] = pa0.z;  As[la_s + 3][la_m] = pa0.w;
        As[la_s + 0][la_m + 64] = pa1.x;  As[la_s + 1][la_m + 64] = pa1.y;
        As[la_s + 2][la_m + 64] = pa1.z;  As[la_s + 3][la_m + 64] = pa1.w;
        Bs[la_s + 0][la_m] = pb0.x;  Bs[la_s + 1][la_m] = pb0.y;
        Bs[la_s + 2][la_m] = pb0.z;  Bs[la_s + 3][la_m] = pb0.w;
        Bs[la_s + 0][la_m + 64] = pb1.x;  Bs[la_s + 1][la_m + 64] = pb1.y;
        Bs[la_s + 2][la_m + 64] = pb1.z;  Bs[la_s + 3][la_m + 64] = pb1.w;
        __syncthreads();

        if (kt + 16 < E_) {
            pa0 = *(const float4*)(xa  + kt + 16);
            pa1 = *(const float4*)(xa2 + kt + 16);
            pb0 = *(const float4*)(wa  + kt + 16);
            pb1 = *(const float4*)(wa2 + kt + 16);
        }

#pragma unroll
        for (int kk = 0; kk < 16; kk++) {
            ulonglong2 b01 = *(const ulonglong2*)&Bs[kk][tx * 8];
            ulonglong2 b23 = *(const ulonglong2*)&Bs[kk][tx * 8 + 4];
            float4 alo = *(const float4*)&As[kk][ty * 8];
            float4 ahi = *(const float4*)&As[kk][ty * 8 + 4];
            float av[8] = {alo.x, alo.y, alo.z, alo.w, ahi.x, ahi.y, ahi.z, ahi.w};
#pragma unroll
            for (int i = 0; i < 8; i++) {
                ull ad;
                DUP2(ad, av[i]);
                FMA2(acc[i][0], ad, b01.x);
                FMA2(acc[i][1], ad, b01.y);
                FMA2(acc[i][2], ad, b23.x);
                FMA2(acc[i][3], ad, b23.y);
            }
        }
        __syncthreads();
    }

    // Epilogue: add bias, scatter into [B,H,NW,P,D]
    const int fb = f0 + tx * 8;       // 8-col group never crosses a 64-col head
    const int hh = fb >> 6;
    const int d0 = fb & 63;
    float bb[8];
#pragma unroll
    for (int j = 0; j < 8; j++) bb[j] = bias[fb + j];

#pragma unroll
    for (int i = 0; i < 8; i++) {
        int m   = m0 + ty * 8 + i;
        int bi  = m / (NW_ * P_);
        int rem = m - bi * (NW_ * P_);
        int ww  = rem / P_;
        int p   = rem - ww * P_;
        float v0, v1, v2, v3, v4, v5, v6, v7;
        UNPK(v0, v1, acc[i][0]);
        UNPK(v2, v3, acc[i][1]);
        UNPK(v4, v5, acc[i][2]);
        UNPK(v6, v7, acc[i][3]);
        float* og = outp + (((size_t)(bi * H_ + hh) * NW_ + ww) * P_ + p) * D_ + d0;
        float4 o0 = make_float4(v0 + bb[0], v1 + bb[1], v2 + bb[2], v3 + bb[3]);
        float4 o1 = make_float4(v4 + bb[4], v5 + bb[5], v6 + bb[6], v7 + bb[7]);
        *(float4*)(og)     = o0;
        *(float4*)(og + 4) = o1;
    }
}

// ---------------------------------------------------------------------------
// Attention: one block (512 threads) per (b,h,w).
// Shared: Qs[160][68] | KV (Kt[64][162] then Vs[160][68]) | Ss[160][161]
// ---------------------------------------------------------------------------
#define SMEM_FLOATS (10880 + 10880 + 25760)
#define SMEM_BYTES  (SMEM_FLOATS * 4)

__global__ __launch_bounds__(512) void attn_kernel(
    const float* __restrict__ pos_bias,
    float* __restrict__ out)
{
    extern __shared__ float smf[];
    float* Qs = smf;            // [160][68]
    float* KV = smf + 10880;    // Kt: [64][162] (10368 used), later Vs: [160][68]
    float* Ss = smf + 21760;    // [160][161]
    __shared__ float pb[19 * 31];
    __shared__ float rsum[160];

    const int w = blockIdx.x, h = blockIdx.y, b = blockIdx.z;
    const int tid = threadIdx.x;
    const int tx = tid & 15, ty = tid >> 4;   // ty 0..31

    for (int i = tid; i < 19 * 31; i += 512) pb[i] = pos_bias[i];

    const size_t base = ((size_t)(b * H_ + h) * NW_ + w) * (P_ * D_);
    const float* qg = g_q + base;
    const float* kg = g_k + base;
    const float* vg = g_v + base;

    // Load Q (pre-scaled) and K transposed (stride 162 for 8B-aligned pairs)
    for (int i = tid; i < P_ * D_ / 4; i += 512) {
        int e = i * 4;
        int p = e >> 6;
        int d = e & 63;
        float4 q4 = *(const float4*)(qg + e);
        q4.x *= 0.125f; q4.y *= 0.125f; q4.z *= 0.125f; q4.w *= 0.125f;
        *(float4*)(Qs + p * 68 + d) = q4;
        float4 k4 = *(const float4*)(kg + e);
        KV[(d + 0) * 162 + p] = k4.x;
        KV[(d + 1) * 162 + p] = k4.y;
        KV[(d + 2) * 162 + p] = k4.z;
        KV[(d + 3) * 162 + p] = k4.w;
    }
    __syncthreads();

    // S = Q K^T : 5x10 microtile per thread (5 rows x 5 col-pairs), f32x2
    const int i0 = ty * 5, j0 = tx * 10;
    ull s2[5][5];
#pragma unroll
    for (int a = 0; a < 5; a++)
#pragma unroll
        for (int c = 0; c < 5; c++) s2[a][c] = 0ull;

    for (int d = 0; d < 64; d++) {
        ull qd[5], kb[5];
#pragma unroll
        for (int a = 0; a < 5; a++) {
            float q = Qs[(i0 + a) * 68 + d];
            DUP2(qd[a], q);
        }
#pragma unroll
        for (int c = 0; c < 5; c++)
            kb[c] = *(const ull*)&KV[d * 162 + j0 + 2 * c];
#pragma unroll
        for (int a = 0; a < 5; a++)
#pragma unroll
            for (int c = 0; c < 5; c++)
                FMA2(s2[a][c], qd[a], kb[c]);
    }

    // Bias + analytic shift-mask, store S
    const int wy = w >> 3, wx = w & 7;
#pragma unroll
    for (int a = 0; a < 5; a++) {
        int i = i0 + a;
        int vi = i >> 4, hi = i & 15;       // p = v*16 + h (WH=16)
#pragma unroll
        for (int c = 0; c < 5; c++) {
            float slo, shi;
            UNPK(slo, shi, s2[a][c]);
#pragma unroll
            for (int t = 0; t < 2; t++) {
                int j = j0 + 2 * c + t;
                int vj = j >> 4, hj = j & 15;
                int dv = vj - vi + 19; if (dv >= 19) dv -= 19;
                int dh = hj - hi + 31; if (dh >= 31) dh -= 31;
                float s = (t ? shi : slo) + pb[dv * 31 + dh];
                bool msk = ((wy == 7) && ((vi < 5) != (vj < 5))) ||
                           ((wx == 7) && ((hi < 8) != (hj < 8)));
                Ss[i * 161 + j] = msk ? -INFINITY : s;
            }
        }
    }
    __syncthreads();

    // Load V into KV region (Kt no longer needed)
    for (int i = tid; i < P_ * D_ / 4; i += 512) {
        int e = i * 4;
        int p = e >> 6;
        int d = e & 63;
        *(float4*)(KV + p * 68 + d) = *(const float4*)(vg + e);
    }

    // Softmax: 16 warps x 10 rows
    const int lane = tid & 31, warp = tid >> 5;
    for (int r = warp; r < P_; r += 16) {
        float vals[5];
        float mx = -INFINITY;
#pragma unroll
        for (int c = 0; c < 5; c++) {
            vals[c] = Ss[r * 161 + lane + 32 * c];
            mx = fmaxf(mx, vals[c]);
        }
#pragma unroll
        for (int o = 16; o > 0; o >>= 1)
            mx = fmaxf(mx, __shfl_xor_sync(0xffffffffu, mx, o));
        float sum = 0.0f;
#pragma unroll
        for (int c = 0; c < 5; c++) {
            float e = __expf(vals[c] - mx);
            vals[c] = e;
            sum += e;
        }
#pragma unroll
        for (int o = 16; o > 0; o >>= 1)
            sum += __shfl_xor_sync(0xffffffffu, sum, o);
#pragma unroll
        for (int c = 0; c < 5; c++) Ss[r * 161 + lane + 32 * c] = vals[c];
        if (lane == 0) rsum[r] = 1.0f / sum;
    }
    __syncthreads();

    // O = P V : 5 rows x 4 cols per thread (2 col-pairs), f32x2
    ull o2[5][2];
#pragma unroll
    for (int a = 0; a < 5; a++) { o2[a][0] = 0ull; o2[a][1] = 0ull; }

    for (int k = 0; k < P_; k++) {
        ulonglong2 vp = *(const ulonglong2*)&KV[k * 68 + tx * 4];
#pragma unroll
        for (int a = 0; a < 5; a++) {
            float s = Ss[(i0 + a) * 161 + k];
            ull sd;
            DUP2(sd, s);
            FMA2(o2[a][0], sd, vp.x);
            FMA2(o2[a][1], sd, vp.y);
        }
    }

    float* og = out + ((size_t)(b * NW_ + w) * P_) * E_ + h * D_ + tx * 4;
#pragma unroll
    for (int a = 0; a < 5; a++) {
        int i = i0 + a;
        float inv = rsum[i];
        float u0, u1, u2, u3;
        UNPK(u0, u1, o2[a][0]);
        UNPK(u2, u3, o2[a][1]);
        float4 o4 = make_float4(u0 * inv, u1 * inv, u2 * inv, u3 * inv);
        *(float4*)(og + (size_t)i * E_) = o4;
    }
}

// ---------------------------------------------------------------------------
extern "C" void kernel_launch(void* const* d_in, const int* in_sizes, int n_in,
                              void* d_out, int out_size)
{
    const float* patches  = (const float*)d_in[0];
    const float* wq       = (const float*)d_in[1];
    const float* bq       = (const float*)d_in[2];
    const float* wk       = (const float*)d_in[3];
    const float* bk       = (const float*)d_in[4];
    const float* wv       = (const float*)d_in[5];
    const float* bv       = (const float*)d_in[6];
    const float* pos_bias = (const float*)d_in[7];
    float* out            = (float*)d_out;

    dim3 g1(M_ / 128, E_ / 128, 3);   // (640, 4, 3)
    qkv_kernel<<<g1, 256>>>(patches, wq, bq, wk, bk, wv, bv);

    cudaFuncSetAttribute(attn_kernel,
                         cudaFuncAttributeMaxDynamicSharedMemorySize, SMEM_BYTES);
    dim3 g2(NW_, H_, B_);             // (64, 8, 8)
    attn_kernel<<<g2, 512, SMEM_BYTES>>>(pos_bias, out);
}

// round 5
// speedup vs baseline: 2.5182x; 2.0260x over previous
#include <cuda_runtime.h>
#include <math.h>
#include <stdint.h>

#define B_  8
#define NW_ 64
#define P_  160
#define E_  512
#define H_  8
#define D_  64
#define M_  (B_*NW_*P_)               // 81920 rows
#define QKV_ELEMS (B_*H_*NW_*P_*D_)   // 41,943,040

typedef unsigned long long ull;

// Scratch for projected Q/K/V in [B,H,NW,P,D] layout
__device__ float g_q[QKV_ELEMS];
__device__ float g_k[QKV_ELEMS];
__device__ float g_v[QKV_ELEMS];

// Packed f32x2 helpers (used in attention)
#define FMA2(c, a, b) asm("fma.rn.f32x2 %0, %1, %2, %3;" : "=l"(c) : "l"(a), "l"(b), "l"(c))
#define DUP2(d, f)    asm("mov.b64 %0, {%1, %1};" : "=l"(d) : "f"(f))
#define UNPK(lo, hi, v) asm("mov.b64 {%0, %1}, %2;" : "=f"(lo), "=f"(hi) : "l"(v))

__device__ __forceinline__ uint32_t smem_u32(const void* p) {
    uint32_t a;
    asm("{ .reg .u64 t; cvta.to.shared.u64 t, %1; cvt.u32.u64 %0, t; }" : "=r"(a) : "l"(p));
    return a;
}

#define CP_ASYNC16(dst, src) \
    asm volatile("cp.async.cg.shared.global [%0], [%1], 16;" :: "r"(dst), "l"(src))
#define CP_COMMIT()  asm volatile("cp.async.commit_group;" ::: "memory")
#define CP_WAIT(n)   asm volatile("cp.async.wait_group %0;" :: "n"(n) : "memory")

__device__ __forceinline__ void mma_tf32(float* c, const uint32_t* a, const uint32_t* b) {
    asm volatile(
        "mma.sync.aligned.m16n8k8.row.col.f32.tf32.tf32.f32 "
        "{%0,%1,%2,%3}, {%4,%5,%6,%7}, {%8,%9}, {%0,%1,%2,%3};"
        : "+f"(c[0]), "+f"(c[1]), "+f"(c[2]), "+f"(c[3])
        : "r"(a[0]), "r"(a[1]), "r"(a[2]), "r"(a[3]), "r"(b[0]), "r"(b[1]));
}

// ---------------------------------------------------------------------------
// QKV projection via tf32 mma.sync: y[m,f] = sum_e x[m,e]*w[f,e] + b[f]
// CTA: 128x128 tile, 8 warps (2x4 m-by-n), warp tile 64x32, BK=16.
// Smem A/B [128][20] fp32 (stride-20 pad: conflict-free frag loads),
// cp.async double-buffered, raw fp32 bits into tf32 MMA (HW truncation).
// ---------------------------------------------------------------------------
#define STRIDE_ 20

__global__ __launch_bounds__(256, 2) void qkv_mma(
    const float* __restrict__ x,
    const float* __restrict__ wq, const float* __restrict__ bq,
    const float* __restrict__ wk, const float* __restrict__ bk,
    const float* __restrict__ wv, const float* __restrict__ bv)
{
    __shared__ float As[2][128][STRIDE_];
    __shared__ float Bs[2][128][STRIDE_];

    const float* wgt; const float* bias; float* outp;
    if (blockIdx.z == 0)      { wgt = wq; bias = bq; outp = g_q; }
    else if (blockIdx.z == 1) { wgt = wk; bias = bk; outp = g_k; }
    else                      { wgt = wv; bias = bv; outp = g_v; }

    const int m0 = blockIdx.x * 128;
    const int f0 = blockIdx.y * 128;
    const int tid = threadIdx.x;
    const int wid = tid >> 5;
    const int lane = tid & 31;
    const int g = lane >> 2;       // group id 0..7
    const int t = lane & 3;        // thread-in-group 0..3

    const int warp_m = (wid & 1) * 64;
    const int warp_n = (wid >> 1) * 32;

    // cp.async thread map: 512 16B-segments per operand, 2 per thread
    const int r0 = tid >> 2,        s0 = (tid & 3) * 4;
    const int r1 = (tid + 256) >> 2, s1 = s0;   // rows 64..127 second pass

    float c[4][4][4];
#pragma unroll
    for (int i = 0; i < 4; i++)
#pragma unroll
        for (int j = 0; j < 4; j++)
#pragma unroll
            for (int k = 0; k < 4; k++) c[i][j][k] = 0.0f;

    const float* xa = x   + (size_t)m0 * E_;
    const float* wa = wgt + (size_t)f0 * E_;

    // Prologue: stage kt=0 into buffer 0
    {
        CP_ASYNC16(smem_u32(&As[0][r0][s0]), xa + (size_t)r0 * E_ + s0);
        CP_ASYNC16(smem_u32(&As[0][r1][s1]), xa + (size_t)r1 * E_ + s1);
        CP_ASYNC16(smem_u32(&Bs[0][r0][s0]), wa + (size_t)r0 * E_ + s0);
        CP_ASYNC16(smem_u32(&Bs[0][r1][s1]), wa + (size_t)r1 * E_ + s1);
        CP_COMMIT();
    }

    int buf = 0;
    for (int kt = 0; kt < E_; kt += 16) {
        if (kt + 16 < E_) {
            const int nb = buf ^ 1;
            const int ko = kt + 16;
            CP_ASYNC16(smem_u32(&As[nb][r0][s0]), xa + (size_t)r0 * E_ + ko + s0);
            CP_ASYNC16(smem_u32(&As[nb][r1][s1]), xa + (size_t)r1 * E_ + ko + s1);
            CP_ASYNC16(smem_u32(&Bs[nb][r0][s0]), wa + (size_t)r0 * E_ + ko + s0);
            CP_ASYNC16(smem_u32(&Bs[nb][r1][s1]), wa + (size_t)r1 * E_ + ko + s1);
            CP_COMMIT();
            CP_WAIT(1);
        } else {
            CP_WAIT(0);
        }
        __syncthreads();

#pragma unroll
        for (int kk = 0; kk < 16; kk += 8) {
            uint32_t a[4][4], b[4][2];
#pragma unroll
            for (int tm = 0; tm < 4; tm++) {
                const float* base = &As[buf][warp_m + tm * 16 + g][kk + t];
                a[tm][0] = *(const uint32_t*)(base);
                a[tm][1] = *(const uint32_t*)(base + 8 * STRIDE_);
                a[tm][2] = *(const uint32_t*)(base + 4);
                a[tm][3] = *(const uint32_t*)(base + 8 * STRIDE_ + 4);
            }
#pragma unroll
            for (int tn = 0; tn < 4; tn++) {
                const float* base = &Bs[buf][warp_n + tn * 8 + g][kk + t];
                b[tn][0] = *(const uint32_t*)(base);
                b[tn][1] = *(const uint32_t*)(base + 4);
            }
#pragma unroll
            for (int tm = 0; tm < 4; tm++)
#pragma unroll
                for (int tn = 0; tn < 4; tn++)
                    mma_tf32(c[tm][tn], a[tm], b[tn]);
        }
        __syncthreads();   // all warps done reading buf before it is re-filled
        buf ^= 1;
    }

    // Epilogue: bias + scatter into [B,H,NW,P,D]
#pragma unroll
    for (int tm = 0; tm < 4; tm++) {
        const int mr0 = m0 + warp_m + tm * 16 + g;
#pragma unroll
        for (int rr = 0; rr < 2; rr++) {
            const int m = mr0 + rr * 8;
            const int bi  = m / (NW_ * P_);
            const int rem = m - bi * (NW_ * P_);
            const int ww  = rem / P_;
            const int p   = rem - ww * P_;
            const size_t rowbase = ((size_t)(bi * H_) * NW_ + ww) * P_ + p;
#pragma unroll
            for (int tn = 0; tn < 4; tn++) {
                const int col = f0 + warp_n + tn * 8 + t * 2;
                const int hh = col >> 6;
                const int d0 = col & 63;
                float2 o;
                o.x = c[tm][tn][rr * 2 + 0] + bias[col];
                o.y = c[tm][tn][rr * 2 + 1] + bias[col + 1];
                *(float2*)(outp + (rowbase + (size_t)hh * NW_ * P_) * D_ + d0) = o;
            }
        }
    }
}

// ---------------------------------------------------------------------------
// Attention: one block (512 threads) per (b,h,w). (unchanged from R4)
// ---------------------------------------------------------------------------
#define SMEM_FLOATS (10880 + 10880 + 25760)
#define SMEM_BYTES  (SMEM_FLOATS * 4)

__global__ __launch_bounds__(512) void attn_kernel(
    const float* __restrict__ pos_bias,
    float* __restrict__ out)
{
    extern __shared__ float smf[];
    float* Qs = smf;            // [160][68]
    float* KV = smf + 10880;    // Kt: [64][162], later Vs: [160][68]
    float* Ss = smf + 21760;    // [160][161]
    __shared__ float pb[19 * 31];
    __shared__ float rsum[160];

    const int w = blockIdx.x, h = blockIdx.y, b = blockIdx.z;
    const int tid = threadIdx.x;
    const int tx = tid & 15, ty = tid >> 4;   // ty 0..31

    for (int i = tid; i < 19 * 31; i += 512) pb[i] = pos_bias[i];

    const size_t base = ((size_t)(b * H_ + h) * NW_ + w) * (P_ * D_);
    const float* qg = g_q + base;
    const float* kg = g_k + base;
    const float* vg = g_v + base;

    for (int i = tid; i < P_ * D_ / 4; i += 512) {
        int e = i * 4;
        int p = e >> 6;
        int d = e & 63;
        float4 q4 = *(const float4*)(qg + e);
        q4.x *= 0.125f; q4.y *= 0.125f; q4.z *= 0.125f; q4.w *= 0.125f;
        *(float4*)(Qs + p * 68 + d) = q4;
        float4 k4 = *(const float4*)(kg + e);
        KV[(d + 0) * 162 + p] = k4.x;
        KV[(d + 1) * 162 + p] = k4.y;
        KV[(d + 2) * 162 + p] = k4.z;
        KV[(d + 3) * 162 + p] = k4.w;
    }
    __syncthreads();

    const int i0 = ty * 5, j0 = tx * 10;
    ull s2[5][5];
#pragma unroll
    for (int a = 0; a < 5; a++)
#pragma unroll
        for (int c = 0; c < 5; c++) s2[a][c] = 0ull;

    for (int d = 0; d < 64; d++) {
        ull qd[5], kb[5];
#pragma unroll
        for (int a = 0; a < 5; a++) {
            float q = Qs[(i0 + a) * 68 + d];
            DUP2(qd[a], q);
        }
#pragma unroll
        for (int c = 0; c < 5; c++)
            kb[c] = *(const ull*)&KV[d * 162 + j0 + 2 * c];
#pragma unroll
        for (int a = 0; a < 5; a++)
#pragma unroll
            for (int c = 0; c < 5; c++)
                FMA2(s2[a][c], qd[a], kb[c]);
    }

    const int wy = w >> 3, wx = w & 7;
#pragma unroll
    for (int a = 0; a < 5; a++) {
        int i = i0 + a;
        int vi = i >> 4, hi = i & 15;
#pragma unroll
        for (int c = 0; c < 5; c++) {
            float slo, shi;
            UNPK(slo, shi, s2[a][c]);
#pragma unroll
            for (int t = 0; t < 2; t++) {
                int j = j0 + 2 * c + t;
                int vj = j >> 4, hj = j & 15;
                int dv = vj - vi + 19; if (dv >= 19) dv -= 19;
                int dh = hj - hi + 31; if (dh >= 31) dh -= 31;
                float s = (t ? shi : slo) + pb[dv * 31 + dh];
                bool msk = ((wy == 7) && ((vi < 5) != (vj < 5))) ||
                           ((wx == 7) && ((hi < 8) != (hj < 8)));
                Ss[i * 161 + j] = msk ? -INFINITY : s;
            }
        }
    }
    __syncthreads();

    for (int i = tid; i < P_ * D_ / 4; i += 512) {
        int e = i * 4;
        int p = e >> 6;
        int d = e & 63;
        *(float4*)(KV + p * 68 + d) = *(const float4*)(vg + e);
    }

    const int lane = tid & 31, warp = tid >> 5;
    for (int r = warp; r < P_; r += 16) {
        float vals[5];
        float mx = -INFINITY;
#pragma unroll
        for (int c = 0; c < 5; c++) {
            vals[c] = Ss[r * 161 + lane + 32 * c];
            mx = fmaxf(mx, vals[c]);
        }
#pragma unroll
        for (int o = 16; o > 0; o >>= 1)
            mx = fmaxf(mx, __shfl_xor_sync(0xffffffffu, mx, o));
        float sum = 0.0f;
#pragma unroll
        for (int c = 0; c < 5; c++) {
            float e = __expf(vals[c] - mx);
            vals[c] = e;
            sum += e;
        }
#pragma unroll
        for (int o = 16; o > 0; o >>= 1)
            sum += __shfl_xor_sync(0xffffffffu, sum, o);
#pragma unroll
        for (int c = 0; c < 5; c++) Ss[r * 161 + lane + 32 * c] = vals[c];
        if (lane == 0) rsum[r] = 1.0f / sum;
    }
    __syncthreads();

    ull o2[5][2];
#pragma unroll
    for (int a = 0; a < 5; a++) { o2[a][0] = 0ull; o2[a][1] = 0ull; }

    for (int k = 0; k < P_; k++) {
        ulonglong2 vp = *(const ulonglong2*)&KV[k * 68 + tx * 4];
#pragma unroll
        for (int a = 0; a < 5; a++) {
            float s = Ss[(i0 + a) * 161 + k];
            ull sd;
            DUP2(sd, s);
            FMA2(o2[a][0], sd, vp.x);
            FMA2(o2[a][1], sd, vp.y);
        }
    }

    float* og = out + ((size_t)(b * NW_ + w) * P_) * E_ + h * D_ + tx * 4;
#pragma unroll
    for (int a = 0; a < 5; a++) {
        int i = i0 + a;
        float inv = rsum[i];
        float u0, u1, u2, u3;
        UNPK(u0, u1, o2[a][0]);
        UNPK(u2, u3, o2[a][1]);
        float4 o4 = make_float4(u0 * inv, u1 * inv, u2 * inv, u3 * inv);
        *(float4*)(og + (size_t)i * E_) = o4;
    }
}

// ---------------------------------------------------------------------------
extern "C" void kernel_launch(void* const* d_in, const int* in_sizes, int n_in,
                              void* d_out, int out_size)
{
    const float* patches  = (const float*)d_in[0];
    const float* wq       = (const float*)d_in[1];
    const float* bq       = (const float*)d_in[2];
    const float* wk       = (const float*)d_in[3];
    const float* bk       = (const float*)d_in[4];
    const float* wv       = (const float*)d_in[5];
    const float* bv       = (const float*)d_in[6];
    const float* pos_bias = (const float*)d_in[7];
    float* out            = (float*)d_out;

    dim3 g1(M_ / 128, E_ / 128, 3);   // (640, 4, 3)
    qkv_mma<<<g1, 256>>>(patches, wq, bq, wk, bk, wv, bv);

    cudaFuncSetAttribute(attn_kernel,
                         cudaFuncAttributeMaxDynamicSharedMemorySize, SMEM_BYTES);
    dim3 g2(NW_, H_, B_);             // (64, 8, 8)
    attn_kernel<<<g2, 512, SMEM_BYTES>>>(pos_bias, out);
}

// round 6
// speedup vs baseline: 2.8041x; 1.1135x over previous
#include <cuda_runtime.h>
#include <math.h>
#include <stdint.h>

#define B_  8
#define NW_ 64
#define P_  160
#define E_  512
#define H_  8
#define D_  64
#define M_  (B_*NW_*P_)               // 81920
#define QKV_ELEMS (B_*H_*NW_*P_*D_)   // 41,943,040

// Scratch
__device__ float g_q[QKV_ELEMS];
__device__ float g_k[QKV_ELEMS];
__device__ float g_v[QKV_ELEMS];
__device__ float g_x[M_*E_];          // rna-rounded patches
__device__ float g_w[3][E_*E_];       // rna-rounded weights

__device__ __forceinline__ uint32_t smem_u32(const void* p) {
    uint32_t a;
    asm("{ .reg .u64 t; cvta.to.shared.u64 t, %1; cvt.u32.u64 %0, t; }" : "=r"(a) : "l"(p));
    return a;
}
__device__ __forceinline__ float rna_tf32(float f) {
    uint32_t r;
    asm("cvt.rna.tf32.f32 %0, %1;" : "=r"(r) : "f"(f));
    return __uint_as_float(r);
}

#define CP_ASYNC16(dst, src) \
    asm volatile("cp.async.cg.shared.global [%0], [%1], 16;" :: "r"(dst), "l"(src))
#define CP_COMMIT()  asm volatile("cp.async.commit_group;" ::: "memory")
#define CP_WAIT(n)   asm volatile("cp.async.wait_group %0;" :: "n"(n) : "memory")

__device__ __forceinline__ void mma_tf32(float* c, const uint32_t* a, const uint32_t* b) {
    asm volatile(
        "mma.sync.aligned.m16n8k8.row.col.f32.tf32.tf32.f32 "
        "{%0,%1,%2,%3}, {%4,%5,%6,%7}, {%8,%9}, {%0,%1,%2,%3};"
        : "+f"(c[0]), "+f"(c[1]), "+f"(c[2]), "+f"(c[3])
        : "r"(a[0]), "r"(a[1]), "r"(a[2]), "r"(a[3]), "r"(b[0]), "r"(b[1]));
}

// ---------------------------------------------------------------------------
// Prepass: rna-round patches and weights to tf32 precision.
// ---------------------------------------------------------------------------
#define XN4 (M_*E_/4)                  // 10,485,760
#define WN4 (E_*E_/4)                  // 65,536
#define TOT4 (XN4 + 3*WN4)

__global__ __launch_bounds__(256) void prepass(
    const float* __restrict__ x,
    const float* __restrict__ wq, const float* __restrict__ wk,
    const float* __restrict__ wv)
{
    int gid = blockIdx.x * 256 + threadIdx.x;
    if (gid >= TOT4) return;
    const float* src;
    float* dst;
    if (gid < XN4) { src = x; dst = g_x; }
    else {
        int j = gid - XN4;
        int which = j / WN4;
        gid = j - which * WN4;
        src = (which == 0) ? wq : (which == 1) ? wk : wv;
        dst = g_w[which];
    }
    float4 v = *(const float4*)(src + (size_t)gid * 4);
    v.x = rna_tf32(v.x); v.y = rna_tf32(v.y);
    v.z = rna_tf32(v.z); v.w = rna_tf32(v.w);
    *(float4*)(dst + (size_t)gid * 4) = v;
}

// ---------------------------------------------------------------------------
// QKV projection via tf32 mma.sync (unchanged core from R5, reads rounded bufs)
// ---------------------------------------------------------------------------
#define STRIDE_ 20

__global__ __launch_bounds__(256, 2) void qkv_mma(
    const float* __restrict__ bq, const float* __restrict__ bk,
    const float* __restrict__ bv)
{
    __shared__ float As[2][128][STRIDE_];
    __shared__ float Bs[2][128][STRIDE_];

    const float* wgt; const float* bias; float* outp;
    if (blockIdx.z == 0)      { wgt = g_w[0]; bias = bq; outp = g_q; }
    else if (blockIdx.z == 1) { wgt = g_w[1]; bias = bk; outp = g_k; }
    else                      { wgt = g_w[2]; bias = bv; outp = g_v; }

    const int m0 = blockIdx.x * 128;
    const int f0 = blockIdx.y * 128;
    const int tid = threadIdx.x;
    const int wid = tid >> 5;
    const int lane = tid & 31;
    const int g = lane >> 2;
    const int t = lane & 3;

    const int warp_m = (wid & 1) * 64;
    const int warp_n = (wid >> 1) * 32;

    const int r0 = tid >> 2,         s0 = (tid & 3) * 4;
    const int r1 = (tid + 256) >> 2, s1 = s0;

    float c[4][4][4];
#pragma unroll
    for (int i = 0; i < 4; i++)
#pragma unroll
        for (int j = 0; j < 4; j++)
#pragma unroll
            for (int k = 0; k < 4; k++) c[i][j][k] = 0.0f;

    const float* xa = g_x + (size_t)m0 * E_;
    const float* wa = wgt + (size_t)f0 * E_;

    {
        CP_ASYNC16(smem_u32(&As[0][r0][s0]), xa + (size_t)r0 * E_ + s0);
        CP_ASYNC16(smem_u32(&As[0][r1][s1]), xa + (size_t)r1 * E_ + s1);
        CP_ASYNC16(smem_u32(&Bs[0][r0][s0]), wa + (size_t)r0 * E_ + s0);
        CP_ASYNC16(smem_u32(&Bs[0][r1][s1]), wa + (size_t)r1 * E_ + s1);
        CP_COMMIT();
    }

    int buf = 0;
    for (int kt = 0; kt < E_; kt += 16) {
        if (kt + 16 < E_) {
            const int nb = buf ^ 1;
            const int ko = kt + 16;
            CP_ASYNC16(smem_u32(&As[nb][r0][s0]), xa + (size_t)r0 * E_ + ko + s0);
            CP_ASYNC16(smem_u32(&As[nb][r1][s1]), xa + (size_t)r1 * E_ + ko + s1);
            CP_ASYNC16(smem_u32(&Bs[nb][r0][s0]), wa + (size_t)r0 * E_ + ko + s0);
            CP_ASYNC16(smem_u32(&Bs[nb][r1][s1]), wa + (size_t)r1 * E_ + ko + s1);
            CP_COMMIT();
            CP_WAIT(1);
        } else {
            CP_WAIT(0);
        }
        __syncthreads();

#pragma unroll
        for (int kk = 0; kk < 16; kk += 8) {
            uint32_t a[4][4], b[4][2];
#pragma unroll
            for (int tm = 0; tm < 4; tm++) {
                const float* base = &As[buf][warp_m + tm * 16 + g][kk + t];
                a[tm][0] = *(const uint32_t*)(base);
                a[tm][1] = *(const uint32_t*)(base + 8 * STRIDE_);
                a[tm][2] = *(const uint32_t*)(base + 4);
                a[tm][3] = *(const uint32_t*)(base + 8 * STRIDE_ + 4);
            }
#pragma unroll
            for (int tn = 0; tn < 4; tn++) {
                const float* base = &Bs[buf][warp_n + tn * 8 + g][kk + t];
                b[tn][0] = *(const uint32_t*)(base);
                b[tn][1] = *(const uint32_t*)(base + 4);
            }
#pragma unroll
            for (int tm = 0; tm < 4; tm++)
#pragma unroll
                for (int tn = 0; tn < 4; tn++)
                    mma_tf32(c[tm][tn], a[tm], b[tn]);
        }
        __syncthreads();
        buf ^= 1;
    }

#pragma unroll
    for (int tm = 0; tm < 4; tm++) {
        const int mr0 = m0 + warp_m + tm * 16 + g;
#pragma unroll
        for (int rr = 0; rr < 2; rr++) {
            const int m = mr0 + rr * 8;
            const int bi  = m / (NW_ * P_);
            const int rem = m - bi * (NW_ * P_);
            const int ww  = rem / P_;
            const int p   = rem - ww * P_;
            const size_t rowbase = ((size_t)(bi * H_) * NW_ + ww) * P_ + p;
#pragma unroll
            for (int tn = 0; tn < 4; tn++) {
                const int col = f0 + warp_n + tn * 8 + t * 2;
                const int hh = col >> 6;
                const int d0 = col & 63;
                float2 o;
                o.x = c[tm][tn][rr * 2 + 0] + bias[col];
                o.y = c[tm][tn][rr * 2 + 1] + bias[col + 1];
                *(float2*)(outp + (rowbase + (size_t)hh * NW_ * P_) * D_ + d0) = o;
            }
        }
    }
}

// ---------------------------------------------------------------------------
// Attention on mma.sync tf32. One CTA (512 thr) per (b,h,w).
// S[160][192pad] = Q[160x64] K^T, bias+mask (cols>=160 -> -inf), softmax,
// O[160][64] = P[160x192] Vt^T.  All operands rna-rounded tf32.
// smem: Qs[160][68] | Ks[192][68] (later Vt[64][196]) | Ss[160][196]
// ---------------------------------------------------------------------------
#define QS_STR 68
#define KS_STR 68
#define SS_STR 196
#define VT_STR 196
#define OFF_KS 10880
#define OFF_SS (10880 + 13056)
#define ATT_SMEM_BYTES ((OFF_SS + 160 * SS_STR) * 4)   // 221184

__global__ __launch_bounds__(512) void attn_mma(
    const float* __restrict__ pos_bias,
    float* __restrict__ out)
{
    extern __shared__ float smf[];
    float* Qs = smf;
    float* Ks = smf + OFF_KS;     // doubles as Vt later
    float* Ss = smf + OFF_SS;
    __shared__ float pb[19 * 31];
    __shared__ float rsum[160];

    const int w = blockIdx.x, h = blockIdx.y, b = blockIdx.z;
    const int tid = threadIdx.x;
    const int lane = tid & 31, warp = tid >> 5;
    const int g = lane >> 2, t = lane & 3;
    const float NEG_INF = __int_as_float(0xff800000);

    for (int i = tid; i < 19 * 31; i += 512) pb[i] = pos_bias[i];

    const size_t base = ((size_t)(b * H_ + h) * NW_ + w) * (P_ * D_);
    const float* qg = g_q + base;
    const float* kg = g_k + base;
    const float* vg = g_v + base;

    // Stage Q (scaled + rna) and K (rna), both row-major
    for (int i = tid; i < P_ * D_ / 4; i += 512) {
        int e = i * 4;
        int p = e >> 6;
        int d = e & 63;
        float4 q4 = *(const float4*)(qg + e);
        q4.x = rna_tf32(q4.x * 0.125f); q4.y = rna_tf32(q4.y * 0.125f);
        q4.z = rna_tf32(q4.z * 0.125f); q4.w = rna_tf32(q4.w * 0.125f);
        *(float4*)(Qs + p * QS_STR + d) = q4;
        float4 k4 = *(const float4*)(kg + e);
        k4.x = rna_tf32(k4.x); k4.y = rna_tf32(k4.y);
        k4.z = rna_tf32(k4.z); k4.w = rna_tf32(k4.w);
        *(float4*)(Ks + p * KS_STR + d) = k4;
    }
    // zero pad key rows 160..191 (contiguous)
    for (int i = tid; i < 32 * KS_STR; i += 512) Ks[160 * KS_STR + i] = 0.0f;
    __syncthreads();

    // ---- S = Q K^T : warp grid 2(m) x 8(n); warp tile 80 x 24
    const int wmS = warp & 1, wnS = warp >> 1;
    const int mS = wmS * 80, nS = wnS * 24;
    float c[5][3][4];
#pragma unroll
    for (int i = 0; i < 5; i++)
#pragma unroll
        for (int j = 0; j < 3; j++)
#pragma unroll
            for (int k = 0; k < 4; k++) c[i][j][k] = 0.0f;

#pragma unroll
    for (int kk = 0; kk < 64; kk += 8) {
        uint32_t a[5][4], bf[3][2];
#pragma unroll
        for (int tm = 0; tm < 5; tm++) {
            const float* ap = &Qs[(mS + tm * 16 + g) * QS_STR + kk + t];
            a[tm][0] = *(const uint32_t*)(ap);
            a[tm][1] = *(const uint32_t*)(ap + 8 * QS_STR);
            a[tm][2] = *(const uint32_t*)(ap + 4);
            a[tm][3] = *(const uint32_t*)(ap + 8 * QS_STR + 4);
        }
#pragma unroll
        for (int tn = 0; tn < 3; tn++) {
            const float* bp = &Ks[(nS + tn * 8 + g) * KS_STR + kk + t];
            bf[tn][0] = *(const uint32_t*)(bp);
            bf[tn][1] = *(const uint32_t*)(bp + 4);
        }
#pragma unroll
        for (int tm = 0; tm < 5; tm++)
#pragma unroll
            for (int tn = 0; tn < 3; tn++)
                mma_tf32(c[tm][tn], a[tm], bf[tn]);
    }

    // Store S with bias + shift-mask; padded cols -> -inf
    const int wy = w >> 3, wx = w & 7;
#pragma unroll
    for (int tm = 0; tm < 5; tm++) {
#pragma unroll
        for (int rr = 0; rr < 2; rr++) {
            const int i = mS + tm * 16 + g + rr * 8;
            const int vi = i >> 4, hi = i & 15;
#pragma unroll
            for (int tn = 0; tn < 3; tn++) {
#pragma unroll
                for (int e2 = 0; e2 < 2; e2++) {
                    const int j = nS + tn * 8 + t * 2 + e2;
                    float sv;
                    if (j >= P_) sv = NEG_INF;
                    else {
                        const int vj = j >> 4, hj = j & 15;
                        int dv = vj - vi + 19; if (dv >= 19) dv -= 19;
                        int dh = hj - hi + 31; if (dh >= 31) dh -= 31;
                        float s = c[tm][tn][rr * 2 + e2] + pb[dv * 31 + dh];
                        bool msk = ((wy == 7) && ((vi < 5) != (vj < 5))) ||
                                   ((wx == 7) && ((hi < 8) != (hj < 8)));
                        sv = msk ? NEG_INF : s;
                    }
                    Ss[i * SS_STR + j] = sv;
                }
            }
        }
    }
    __syncthreads();

    // Stage Vt (transpose + rna) into Ks region; zero pad cols 160..191
    float* Vt = Ks;
    for (int i = tid; i < P_ * D_ / 4; i += 512) {
        int e = i * 4;
        int p = e >> 6;
        int d = e & 63;
        float4 v4 = *(const float4*)(vg + e);
        Vt[(d + 0) * VT_STR + p] = rna_tf32(v4.x);
        Vt[(d + 1) * VT_STR + p] = rna_tf32(v4.y);
        Vt[(d + 2) * VT_STR + p] = rna_tf32(v4.z);
        Vt[(d + 3) * VT_STR + p] = rna_tf32(v4.w);
    }
    for (int i = tid; i < 64 * 32; i += 512) {
        int d = i >> 5, pp = 160 + (i & 31);
        Vt[d * VT_STR + pp] = 0.0f;
    }

    // Softmax over 192 cols (pads are -inf -> exp 0); P stored rna-rounded
    for (int r = warp; r < P_; r += 16) {
        float vals[6];
        float mx = NEG_INF;
#pragma unroll
        for (int s6 = 0; s6 < 6; s6++) {
            vals[s6] = Ss[r * SS_STR + lane + 32 * s6];
            mx = fmaxf(mx, vals[s6]);
        }
#pragma unroll
        for (int o = 16; o > 0; o >>= 1)
            mx = fmaxf(mx, __shfl_xor_sync(0xffffffffu, mx, o));
        float sum = 0.0f;
#pragma unroll
        for (int s6 = 0; s6 < 6; s6++) {
            float e = __expf(vals[s6] - mx);
            vals[s6] = e;
            sum += e;
        }
#pragma unroll
        for (int o = 16; o > 0; o >>= 1)
            sum += __shfl_xor_sync(0xffffffffu, sum, o);
#pragma unroll
        for (int s6 = 0; s6 < 6; s6++)
            Ss[r * SS_STR + lane + 32 * s6] = rna_tf32(vals[s6]);
        if (lane == 0) rsum[r] = 1.0f / sum;
    }
    __syncthreads();

    // ---- O = P Vt^T : warp grid 2(m) x 8(n); warp tile 80 x 8, K=192
    const int wmO = warp >> 3, wnO = warp & 7;
    const int mO = wmO * 80, nO = wnO * 8;
    float o[5][4];
#pragma unroll
    for (int i = 0; i < 5; i++)
#pragma unroll
        for (int k = 0; k < 4; k++) o[i][k] = 0.0f;

    for (int ks = 0; ks < 192; ks += 8) {
        uint32_t a[5][4], bf[2];
#pragma unroll
        for (int tm = 0; tm < 5; tm++) {
            const float* ap = &Ss[(mO + tm * 16 + g) * SS_STR + ks + t];
            a[tm][0] = *(const uint32_t*)(ap);
            a[tm][1] = *(const uint32_t*)(ap + 8 * SS_STR);
            a[tm][2] = *(const uint32_t*)(ap + 4);
            a[tm][3] = *(const uint32_t*)(ap + 8 * SS_STR + 4);
        }
        {
            const float* bp = &Vt[(nO + g) * VT_STR + ks + t];
            bf[0] = *(const uint32_t*)(bp);
            bf[1] = *(const uint32_t*)(bp + 4);
        }
#pragma unroll
        for (int tm = 0; tm < 5; tm++)
            mma_tf32(o[tm], a[tm], bf);
    }

    // Epilogue: normalize by row sums, write out
#pragma unroll
    for (int tm = 0; tm < 5; tm++) {
#pragma unroll
        for (int rr = 0; rr < 2; rr++) {
            const int p = mO + tm * 16 + g + rr * 8;
            const float inv = rsum[p];
            float2 o2;
            o2.x = o[tm][rr * 2 + 0] * inv;
            o2.y = o[tm][rr * 2 + 1] * inv;
            *(float2*)(out + ((size_t)(b * NW_ + w) * P_ + p) * E_ + h * D_ + nO + t * 2) = o2;
        }
    }
}

// ---------------------------------------------------------------------------
extern "C" void kernel_launch(void* const* d_in, const int* in_sizes, int n_in,
                              void* d_out, int out_size)
{
    const float* patches  = (const float*)d_in[0];
    const float* wq       = (const float*)d_in[1];
    const float* bq       = (const float*)d_in[2];
    const float* wk       = (const float*)d_in[3];
    const float* bk       = (const float*)d_in[4];
    const float* wv       = (const float*)d_in[5];
    const float* bv       = (const float*)d_in[6];
    const float* pos_bias = (const float*)d_in[7];
    float* out            = (float*)d_out;

    prepass<<<(TOT4 + 255) / 256, 256>>>(patches, wq, wk, wv);

    dim3 g1(M_ / 128, E_ / 128, 3);   // (640, 4, 3)
    qkv_mma<<<g1, 256>>>(bq, bk, bv);

    cudaFuncSetAttribute(attn_mma,
                         cudaFuncAttributeMaxDynamicSharedMemorySize, ATT_SMEM_BYTES);
    dim3 g2(NW_, H_, B_);             // (64, 8, 8)
    attn_mma<<<g2, 512, ATT_SMEM_BYTES>>>(pos_bias, out);
}